// round 9
// baseline (speedup 1.0000x reference)
#include <cuda_runtime.h>
#include <cuda_fp16.h>
#include <cstdint>

// ---------------- scratch (static device globals; no allocation) ----------------
__device__ float  g_C[180000ull * 1024ull];     // [K|Q] projections fp32
__device__ __half g_Ah[180224ull * 512ull];     // fp16-hi of embeddings (padded rows)
__device__ __half g_Al[180224ull * 512ull];     // fp16-lo
__device__ __half g_Bh[1024 * 512];             // fp16-hi of [Wk;Wq] rows (n-major)
__device__ __half g_Bl[1024 * 512];             // fp16-lo
__device__ float  g_bcat[1024];
__device__ int    g_flag[30000];                // near-tie nodes needing fp32 fixup

static constexpr int M_ROWS = 180000;           // 30000 nodes * 6
static constexpr int M_PAD  = 180224;

// ---------------- PTX helpers ----------------
__device__ __forceinline__ uint32_t smem_u32(const void* p) {
    uint32_t a;
    asm("{ .reg .u64 t; cvta.to.shared.u64 t, %1; cvt.u32.u64 %0, t; }" : "=r"(a) : "l"(p));
    return a;
}
__device__ __forceinline__ void cp16(uint32_t dst, const void* src) {
    asm volatile("cp.async.cg.shared.global [%0], [%1], 16;"
                 :: "r"(dst), "l"(__cvta_generic_to_global(src)) : "memory");
}
__device__ __forceinline__ void cp_commit() {
    asm volatile("cp.async.commit_group;" ::: "memory");
}
__device__ __forceinline__ void cp_wait1() {
    asm volatile("cp.async.wait_group 1;" ::: "memory");
}
__device__ __forceinline__ void ldsm_x4(uint32_t* r, uint32_t addr) {
    asm volatile("ldmatrix.sync.aligned.m8n8.x4.shared.b16 {%0,%1,%2,%3}, [%4];"
                 : "=r"(r[0]), "=r"(r[1]), "=r"(r[2]), "=r"(r[3]) : "r"(addr));
}
__device__ __forceinline__ void mma16816(float* d, const uint32_t* a, const uint32_t* b) {
    asm volatile("mma.sync.aligned.m16n8k16.row.col.f32.f16.f16.f32 "
                 "{%0,%1,%2,%3}, {%4,%5,%6,%7}, {%8,%9}, {%0,%1,%2,%3};"
                 : "+f"(d[0]), "+f"(d[1]), "+f"(d[2]), "+f"(d[3])
                 : "r"(a[0]), "r"(a[1]), "r"(a[2]), "r"(a[3]), "r"(b[0]), "r"(b[1]));
}

// ---------------- pack weights: fp16 hi/lo split + bias concat ----------------
__global__ void pack_w(const float* __restrict__ Wk, const float* __restrict__ bk,
                       const float* __restrict__ Wq, const float* __restrict__ bq) {
    int idx = blockIdx.x * blockDim.x + threadIdx.x;
    if (idx < 1024 * 512) {
        int n = idx >> 9, k = idx & 511;
        float w = (n < 512) ? Wk[n * 512 + k] : Wq[(n - 512) * 512 + k];
        __half h = __float2half_rn(w);
        __half l = __float2half_rn(w - __half2float(h));
        g_Bh[idx] = h;
        g_Bl[idx] = l;
    }
    if (idx < 1024) g_bcat[idx] = (idx < 512) ? bk[idx] : bq[idx - 512];
}

// ---------------- split A: fp16 hi/lo (padded, zero tail) + zero flags ----------------
__global__ void split_a(const float* __restrict__ X) {
    const int n4 = (M_ROWS * 512) / 4;
    const int p4 = (M_PAD * 512) / 4;
    int i = blockIdx.x * blockDim.x + threadIdx.x;
    if (i < 30000) g_flag[i] = 0;
    if (i < n4) {
        float4 v = ((const float4*)X)[i];
        __half2 h01 = __floats2half2_rn(v.x, v.y);
        __half2 h23 = __floats2half2_rn(v.z, v.w);
        float2 f01 = __half22float2(h01);
        float2 f23 = __half22float2(h23);
        __half2 l01 = __floats2half2_rn(v.x - f01.x, v.y - f01.y);
        __half2 l23 = __floats2half2_rn(v.z - f23.x, v.w - f23.y);
        ((__half2*)g_Ah)[2 * i] = h01;
        ((__half2*)g_Ah)[2 * i + 1] = h23;
        ((__half2*)g_Al)[2 * i] = l01;
        ((__half2*)g_Al)[2 * i + 1] = l23;
    } else if (i < p4) {
        __half2 z = __floats2half2_rn(0.f, 0.f);
        ((__half2*)g_Ah)[2 * i] = z;
        ((__half2*)g_Ah)[2 * i + 1] = z;
        ((__half2*)g_Al)[2 * i] = z;
        ((__half2*)g_Al)[2 * i + 1] = z;
    }
}

// ---------------- GEMM: C[M,1024] = X @ W^T + b via 3x fp16-split mma.sync ----------------
// CTA tile 128x256, 256 threads, 8 warps (2x4), warp tile 64x64, BK=32, 3-stage pipeline.
// Stage: Ah[128*80] Al[128*80] Bh[256*80] Bl[256*80] = 61440 B; 3 stages = 184320 B.
static constexpr int STAGE_B = 61440;
static constexpr int SMEM_GEMM = 3 * STAGE_B;

__global__ __launch_bounds__(256, 1) void gemm_kernel(int M) {
    extern __shared__ char smem[];
    const uint32_t smem_base = smem_u32(smem);
    const int tid = threadIdx.x;
    const int l = tid & 31, wid = tid >> 5;
    const int wm = wid >> 2, wn = wid & 3;          // 2x4 warp grid, warp tile 64x64
    const int n0 = blockIdx.x * 256, m0 = blockIdx.y * 128;

    // ldmatrix per-lane base offsets (80B row stride)
    const uint32_t aoff =
        (uint32_t)((wm * 64 + ((l >> 3) & 1) * 8 + (l & 7)) * 80 + (l >> 4) * 16);
    const uint32_t boff =
        (uint32_t)((wn * 64 + (l >> 4) * 8 + (l & 7)) * 80 + ((l >> 3) & 1) * 16);

    const int srow = tid >> 2, sc = tid & 3;        // staging: row 0..63 (+strides), 16B chunk

    float acc[4][8][4];
#pragma unroll
    for (int mt = 0; mt < 4; mt++)
#pragma unroll
        for (int nt = 0; nt < 8; nt++)
#pragma unroll
            for (int q = 0; q < 4; q++) acc[mt][nt][q] = 0.f;

    auto stage_load = [&](int chunk, int stg) {
        const uint32_t sb = smem_base + (uint32_t)stg * STAGE_B;
        const int kk = chunk * 32;
        // A: 128 rows (hi+lo)
#pragma unroll
        for (int j = 0; j < 2; j++) {
            int row = srow + j * 64;
            uint32_t soff = (uint32_t)(row * 80 + sc * 16);
            size_t ga = (size_t)(m0 + row) * 512 + kk + sc * 8;
            cp16(sb + soff, g_Ah + ga);
            cp16(sb + 10240 + soff, g_Al + ga);
        }
        // B: 256 rows (hi+lo)
#pragma unroll
        for (int j = 0; j < 4; j++) {
            int row = srow + j * 64;
            uint32_t soff = (uint32_t)(row * 80 + sc * 16);
            size_t gb = (size_t)(n0 + row) * 512 + kk + sc * 8;
            cp16(sb + 20480 + soff, g_Bh + gb);
            cp16(sb + 40960 + soff, g_Bl + gb);
        }
        cp_commit();
    };

    stage_load(0, 0);
    stage_load(1, 1);

    for (int c = 0; c < 16; c++) {
        cp_wait1();
        __syncthreads();
        if (c + 2 < 16) stage_load(c + 2, (c + 2) % 3);
        else cp_commit();                           // keep group count in lockstep

        const uint32_t sb = smem_base + (uint32_t)(c % 3) * STAGE_B;
#pragma unroll
        for (int ks = 0; ks < 2; ks++) {
            uint32_t ah[4][4], al[4][4];
#pragma unroll
            for (int mt = 0; mt < 4; mt++) {
                ldsm_x4(ah[mt], sb + aoff + mt * 1280 + ks * 32);
                ldsm_x4(al[mt], sb + 10240 + aoff + mt * 1280 + ks * 32);
            }
#pragma unroll
            for (int p = 0; p < 4; p++) {
                uint32_t bh[4], bl[4];
                ldsm_x4(bh, sb + 20480 + boff + p * 1280 + ks * 32);
                ldsm_x4(bl, sb + 40960 + boff + p * 1280 + ks * 32);
                // three split terms; same-acc reuse distance = 8 MMAs
#pragma unroll
                for (int mt = 0; mt < 4; mt++)
#pragma unroll
                    for (int h = 0; h < 2; h++)
                        mma16816(acc[mt][p * 2 + h], ah[mt], &bh[h * 2]);
#pragma unroll
                for (int mt = 0; mt < 4; mt++)
#pragma unroll
                    for (int h = 0; h < 2; h++)
                        mma16816(acc[mt][p * 2 + h], ah[mt], &bl[h * 2]);
#pragma unroll
                for (int mt = 0; mt < 4; mt++)
#pragma unroll
                    for (int h = 0; h < 2; h++)
                        mma16816(acc[mt][p * 2 + h], al[mt], &bh[h * 2]);
            }
        }
    }

    // epilogue: bias + fp32 store
    const int er = m0 + wm * 64 + (l >> 2);
    const int ec = n0 + wn * 64 + (l & 3) * 2;
#pragma unroll
    for (int mt = 0; mt < 4; mt++) {
        int r0 = er + mt * 16, r1 = r0 + 8;
#pragma unroll
        for (int nt = 0; nt < 8; nt++) {
            int cc = ec + nt * 8;
            float2 bi = *(const float2*)&g_bcat[cc];
            if (r0 < M) {
                float2 o = make_float2(acc[mt][nt][0] + bi.x, acc[mt][nt][1] + bi.y);
                *(float2*)&g_C[(size_t)r0 * 1024 + cc] = o;
            }
            if (r1 < M) {
                float2 o = make_float2(acc[mt][nt][2] + bi.x, acc[mt][nt][3] + bi.y);
                *(float2*)&g_C[(size_t)r1 * 1024 + cc] = o;
            }
        }
    }
}

// ---------------- attention kernel: one block per node + near-tie flagging ----------------
#define STR 516
__global__ __launch_bounds__(288) void attn_kernel(
    const float* __restrict__ emb, const float* __restrict__ ac,
    const float* __restrict__ Wg, const float* __restrict__ bg,
    const int* __restrict__ batch,
    float* __restrict__ ctx_out, float* __restrict__ att_out) {
    __shared__ float q[6][STR], k[6][STR], v[6][STR];
    __shared__ float sc[8][6][6];
    __shared__ float at[8][6][6];
    __shared__ float g[6];

    const int n = blockIdx.x;
    const int tid = threadIdx.x;
    const float* Crow = g_C + (size_t)n * 6 * 1024;
    const float* Vrow = emb + (size_t)n * 6 * 512;

    for (int i = tid; i < 768; i += 288) {
        int t = i >> 7;
        int c4 = i & 127;
        float4 kv = *(const float4*)(Crow + t * 1024 + c4 * 4);
        float4 qv = *(const float4*)(Crow + t * 1024 + 512 + c4 * 4);
        float4 vv = *(const float4*)(Vrow + t * 512 + c4 * 4);
        *(float4*)&k[t][c4 * 4] = kv;
        *(float4*)&q[t][c4 * 4] = qv;
        *(float4*)&v[t][c4 * 4] = vv;
    }
    if (tid < 6) {
        int b = batch[n];
        float s = bg[tid];
#pragma unroll
        for (int j = 0; j < 5; j++) s += ac[b * 5 + j] * Wg[tid * 5 + j];
        g[tid] = s;
    }
    __syncthreads();

    {
        int h = tid / 36;
        int r = tid % 36;
        int t = r / 6;
        int s = r % 6;
        const float4* qp = (const float4*)&q[t][h * 64];
        const float4* kp = (const float4*)&k[s][h * 64];
        float acc = 0.f;
#pragma unroll
        for (int d = 0; d < 16; d++) {
            float4 a = qp[d];
            float4 b = kp[d];
            acc += a.x * b.x + a.y * b.y + a.z * b.z + a.w * b.w;
        }
        sc[h][t][s] = acc * 0.125f * g[s];
    }
    __syncthreads();

    if (tid < 48) {
        int h = tid / 6;
        int t = tid % 6;
        float a[6];
#pragma unroll
        for (int s = 0; s < 6; s++) a[s] = sc[h][t][s];
        bool keep[6];
        float a4 = 0.f, a5 = 0.f;
#pragma unroll
        for (int s = 0; s < 6; s++) {
            float as = fabsf(a[s]);
            int cnt = 0;
#pragma unroll
            for (int j = 0; j < 6; j++) {
                float aj = fabsf(a[j]);
                cnt += (aj > as) || (aj == as && j < s);
            }
            keep[s] = (cnt < 4);
            if (cnt == 3) a4 = as;
            if (cnt == 4) a5 = as;
        }
        // near-tie at the top-4 boundary: flag node for exact fp32 fixup
        if (a4 - a5 <= a4 * 1e-4f + 1e-7f) g_flag[n] = 1;

        float mx = -3.402823466e38f;
#pragma unroll
        for (int s = 0; s < 6; s++)
            if (keep[s]) mx = fmaxf(mx, a[s]);
        float e[6];
        float sum = 0.f;
#pragma unroll
        for (int s = 0; s < 6; s++) {
            e[s] = keep[s] ? expf(a[s] - mx) : 0.f;
            sum += e[s];
        }
        float inv = 1.f / sum;
#pragma unroll
        for (int s = 0; s < 6; s++) {
            float w = e[s] * inv;
            at[h][t][s] = w;
            if (att_out) att_out[(size_t)n * 288 + h * 36 + t * 6 + s] = w;
        }
    }
    __syncthreads();

    if (ctx_out) {
        for (int e = tid; e < 3072; e += 288) {
            int t = e >> 9;
            int c = e & 511;
            int h = c >> 6;
            float acc = 0.f;
#pragma unroll
            for (int s = 0; s < 6; s++) acc += at[h][t][s] * v[s][c];
            ctx_out[(size_t)n * 3072 + e] = acc;
        }
    }
}

// ---------------- fixup: exact fp32 recompute for flagged nodes ----------------
__global__ __launch_bounds__(288) void fixup_kernel(
    const float* __restrict__ emb, const float* __restrict__ ac,
    const float* __restrict__ Wk, const float* __restrict__ bk,
    const float* __restrict__ Wq, const float* __restrict__ bq,
    const float* __restrict__ Wg, const float* __restrict__ bg,
    const int* __restrict__ batch,
    float* __restrict__ ctx_out, float* __restrict__ att_out) {
    const int n = blockIdx.x;
    if (g_flag[n] == 0) return;

    __shared__ float x[6][512];
    __shared__ float kq[6][1024];
    __shared__ float sc[8][6][6];
    __shared__ float at[8][6][6];
    __shared__ float g[6];

    const int tid = threadIdx.x;
    const float* Xrow = emb + (size_t)n * 6 * 512;

    for (int i = tid; i < 768; i += 288) {
        int t = i >> 7, c4 = i & 127;
        *(float4*)&x[t][c4 * 4] = *(const float4*)(Xrow + t * 512 + c4 * 4);
    }
    if (tid < 6) {
        int b = batch[n];
        float s = bg[tid];
#pragma unroll
        for (int j = 0; j < 5; j++) s += ac[b * 5 + j] * Wg[tid * 5 + j];
        g[tid] = s;
    }
    __syncthreads();

    for (int idx = tid; idx < 6144; idx += 288) {
        int t = idx >> 10, j = idx & 1023;
        const float* w = (j < 512) ? (Wk + (size_t)j * 512) : (Wq + (size_t)(j - 512) * 512);
        float acc = (j < 512) ? bk[j] : bq[j - 512];
        const float4* wv = (const float4*)w;
        const float4* xv = (const float4*)&x[t][0];
#pragma unroll 4
        for (int d = 0; d < 128; d++) {
            float4 a = wv[d];
            float4 b = xv[d];
            acc += a.x * b.x + a.y * b.y + a.z * b.z + a.w * b.w;
        }
        kq[t][j] = acc;
    }
    __syncthreads();

    {
        int h = tid / 36;
        int r = tid % 36;
        int t = r / 6;
        int s = r % 6;
        const float* qp = &kq[t][512 + h * 64];
        const float* kp = &kq[s][h * 64];
        float acc = 0.f;
#pragma unroll
        for (int d = 0; d < 64; d++) acc += qp[d] * kp[d];
        sc[h][t][s] = acc * 0.125f * g[s];
    }
    __syncthreads();

    if (tid < 48) {
        int h = tid / 6;
        int t = tid % 6;
        float a[6];
#pragma unroll
        for (int s = 0; s < 6; s++) a[s] = sc[h][t][s];
        bool keep[6];
#pragma unroll
        for (int s = 0; s < 6; s++) {
            float as = fabsf(a[s]);
            int cnt = 0;
#pragma unroll
            for (int j = 0; j < 6; j++) {
                float aj = fabsf(a[j]);
                cnt += (aj > as) || (aj == as && j < s);
            }
            keep[s] = (cnt < 4);
        }
        float mx = -3.402823466e38f;
#pragma unroll
        for (int s = 0; s < 6; s++)
            if (keep[s]) mx = fmaxf(mx, a[s]);
        float e[6];
        float sum = 0.f;
#pragma unroll
        for (int s = 0; s < 6; s++) {
            e[s] = keep[s] ? expf(a[s] - mx) : 0.f;
            sum += e[s];
        }
        float inv = 1.f / sum;
#pragma unroll
        for (int s = 0; s < 6; s++) {
            float w = e[s] * inv;
            at[h][t][s] = w;
            if (att_out) att_out[(size_t)n * 288 + h * 36 + t * 6 + s] = w;
        }
    }
    __syncthreads();

    if (ctx_out) {
        for (int e = tid; e < 3072; e += 288) {
            int t = e >> 9;
            int c = e & 511;
            int h = c >> 6;
            float acc = 0.f;
#pragma unroll
            for (int s = 0; s < 6; s++) acc += at[h][t][s] * x[s][c];
            ctx_out[(size_t)n * 3072 + e] = acc;
        }
    }
}

// ---------------- launch ----------------
extern "C" void kernel_launch(void* const* d_in, const int* in_sizes, int n_in,
                              void* d_out, int out_size) {
    const float* emb = (const float*)d_in[0];
    const float* ac = (const float*)d_in[1];
    const float* Wk = (const float*)d_in[2];
    const float* bk = (const float*)d_in[3];
    const float* Wq = (const float*)d_in[4];
    const float* bq = (const float*)d_in[5];
    const float* Wg = (const float*)d_in[6];
    const float* bg = (const float*)d_in[7];
    const int* batch = (const int*)d_in[8];

    int nNodes = in_sizes[8];  // 30000
    int M = nNodes * 6;        // 180000

    float* out = (float*)d_out;
    long long CTX = (long long)nNodes * 6 * 512;
    long long ATT = (long long)nNodes * 8 * 36;
    float* ctx_out = nullptr;
    float* att_out = nullptr;
    if ((long long)out_size >= CTX + ATT) {
        ctx_out = out;
        att_out = out + CTX;
    } else if ((long long)out_size >= CTX) {
        ctx_out = out;
    } else {
        att_out = out;
    }

    cudaFuncSetAttribute(gemm_kernel, cudaFuncAttributeMaxDynamicSharedMemorySize,
                         SMEM_GEMM);

    pack_w<<<2048, 256>>>(Wk, bk, Wq, bq);
    int p4 = (M_PAD * 512) / 4;
    split_a<<<(p4 + 255) / 256, 256>>>(emb);
    dim3 gg(4, (M + 127) / 128);
    gemm_kernel<<<gg, 256, SMEM_GEMM>>>(M);
    attn_kernel<<<nNodes, 288>>>(emb, ac, Wg, bg, batch, ctx_out, att_out);
    fixup_kernel<<<nNodes, 288>>>(emb, ac, Wk, bk, Wq, bq, Wg, bg, batch,
                                  ctx_out, att_out);
}

// round 11
// speedup vs baseline: 1.1206x; 1.1206x over previous
#include <cuda_runtime.h>
#include <cuda_fp16.h>
#include <cstdint>

// ---------------- scratch (static device globals; no allocation) ----------------
__device__ float  g_C[180000ull * 1024ull];     // [K|Q] projections fp32
__device__ __half g_Ah[180224ull * 512ull];     // fp16-hi of embeddings (padded rows)
__device__ __half g_Al[180224ull * 512ull];     // fp16-lo
__device__ __half g_Bh[1024 * 512];             // fp16-hi of [Wk;Wq] rows (n-major)
__device__ __half g_Bl[1024 * 512];             // fp16-lo
__device__ float  g_bcat[1024];
__device__ int    g_flag[30000];                // near-tie nodes needing fp32 fixup

static constexpr int M_ROWS = 180000;           // 30000 nodes * 6
static constexpr int M_PAD  = 180224;

// ---------------- PTX helpers ----------------
__device__ __forceinline__ uint32_t smem_u32(const void* p) {
    uint32_t a;
    asm("{ .reg .u64 t; cvta.to.shared.u64 t, %1; cvt.u32.u64 %0, t; }" : "=r"(a) : "l"(p));
    return a;
}
__device__ __forceinline__ void cp16(uint32_t dst, const void* src) {
    asm volatile("cp.async.cg.shared.global [%0], [%1], 16;"
                 :: "r"(dst), "l"(__cvta_generic_to_global(src)) : "memory");
}
__device__ __forceinline__ void cp_commit() {
    asm volatile("cp.async.commit_group;" ::: "memory");
}
__device__ __forceinline__ void cp_wait2() {
    asm volatile("cp.async.wait_group 2;" ::: "memory");
}
__device__ __forceinline__ void ldsm_x4(uint32_t* r, uint32_t addr) {
    asm volatile("ldmatrix.sync.aligned.m8n8.x4.shared.b16 {%0,%1,%2,%3}, [%4];"
                 : "=r"(r[0]), "=r"(r[1]), "=r"(r[2]), "=r"(r[3]) : "r"(addr));
}
__device__ __forceinline__ void mma16816(float* d, const uint32_t* a, const uint32_t* b) {
    asm volatile("mma.sync.aligned.m16n8k16.row.col.f32.f16.f16.f32 "
                 "{%0,%1,%2,%3}, {%4,%5,%6,%7}, {%8,%9}, {%0,%1,%2,%3};"
                 : "+f"(d[0]), "+f"(d[1]), "+f"(d[2]), "+f"(d[3])
                 : "r"(a[0]), "r"(a[1]), "r"(a[2]), "r"(a[3]), "r"(b[0]), "r"(b[1]));
}

// ---------------- pack weights: fp16 hi/lo split + bias concat ----------------
__global__ void pack_w(const float* __restrict__ Wk, const float* __restrict__ bk,
                       const float* __restrict__ Wq, const float* __restrict__ bq) {
    int idx = blockIdx.x * blockDim.x + threadIdx.x;
    if (idx < 1024 * 512) {
        int n = idx >> 9, k = idx & 511;
        float w = (n < 512) ? Wk[n * 512 + k] : Wq[(n - 512) * 512 + k];
        __half h = __float2half_rn(w);
        __half l = __float2half_rn(w - __half2float(h));
        g_Bh[idx] = h;
        g_Bl[idx] = l;
    }
    if (idx < 1024) g_bcat[idx] = (idx < 512) ? bk[idx] : bq[idx - 512];
}

// ---------------- split A: fp16 hi/lo (padded, zero tail) + zero flags ----------------
__global__ void split_a(const float* __restrict__ X) {
    const int n4 = (M_ROWS * 512) / 4;
    const int p4 = (M_PAD * 512) / 4;
    int i = blockIdx.x * blockDim.x + threadIdx.x;
    if (i < 30000) g_flag[i] = 0;
    if (i < n4) {
        float4 v = ((const float4*)X)[i];
        __half2 h01 = __floats2half2_rn(v.x, v.y);
        __half2 h23 = __floats2half2_rn(v.z, v.w);
        float2 f01 = __half22float2(h01);
        float2 f23 = __half22float2(h23);
        __half2 l01 = __floats2half2_rn(v.x - f01.x, v.y - f01.y);
        __half2 l23 = __floats2half2_rn(v.z - f23.x, v.w - f23.y);
        ((__half2*)g_Ah)[2 * i] = h01;
        ((__half2*)g_Ah)[2 * i + 1] = h23;
        ((__half2*)g_Al)[2 * i] = l01;
        ((__half2*)g_Al)[2 * i + 1] = l23;
    } else if (i < p4) {
        __half2 z = __floats2half2_rn(0.f, 0.f);
        ((__half2*)g_Ah)[2 * i] = z;
        ((__half2*)g_Ah)[2 * i + 1] = z;
        ((__half2*)g_Al)[2 * i] = z;
        ((__half2*)g_Al)[2 * i + 1] = z;
    }
}

// ---------------- GEMM: C[M,1024] = X @ W^T + b via 3x fp16-split mma.sync ----------------
// CTA tile 128x128, 256 threads, warp tile 32x64 (4x2 warp grid), BK=32.
// 64B rows with XOR swizzle (chunk ^= (row>>1)&3) -> stage 32768 B; 3 stages -> 2 CTAs/SM.
static constexpr int STAGE_B = 32768;
static constexpr int SMEM_GEMM = 3 * STAGE_B;

__global__ __launch_bounds__(256, 2) void gemm_kernel(int M) {
    extern __shared__ char smem[];
    const uint32_t smem_base = smem_u32(smem);
    const int tid = threadIdx.x;
    const int l = tid & 31, wid = tid >> 5;
    const int wm = wid >> 1, wn = wid & 1;          // 4x2 warp grid, tile 32x64
    const int n0 = blockIdx.x * 128, m0 = blockIdx.y * 128;

    // ldmatrix lane constants (64B rows, swizzled chunk)
    const int arow = wm * 32 + ((l >> 3) & 1) * 8 + (l & 7);
    const uint32_t a_rb = (uint32_t)(arow * 64);
    const int a_sw = (arow >> 1) & 3;
    const int a_bc = (l >> 4);                      // 16B column within k-chunk pair
    const int brow = wn * 64 + (l >> 4) * 8 + (l & 7);
    const uint32_t b_rb = (uint32_t)(brow * 64);
    const int b_sw = (brow >> 1) & 3;
    const int b_bc = (l >> 3) & 1;

    const int srow = tid >> 2, sc = tid & 3;        // staging: row 0..63(+64), 16B chunk

    float acc[2][8][4];
#pragma unroll
    for (int mt = 0; mt < 2; mt++)
#pragma unroll
        for (int nt = 0; nt < 8; nt++)
#pragma unroll
            for (int q = 0; q < 4; q++) acc[mt][nt][q] = 0.f;

    auto stage_load = [&](int chunk, int stg) {
        const uint32_t sb = smem_base + (uint32_t)stg * STAGE_B;
        const int kk = chunk * 32;
#pragma unroll
        for (int j = 0; j < 2; j++) {
            int row = srow + j * 64;
            uint32_t soff = (uint32_t)(row * 64 + ((sc ^ ((row >> 1) & 3)) << 4));
            size_t ga = (size_t)(m0 + row) * 512 + kk + sc * 8;
            size_t gb = (size_t)(n0 + row) * 512 + kk + sc * 8;
            cp16(sb + soff, g_Ah + ga);
            cp16(sb + 8192 + soff, g_Al + ga);
            cp16(sb + 16384 + soff, g_Bh + gb);
            cp16(sb + 24576 + soff, g_Bl + gb);
        }
        cp_commit();
    };

    stage_load(0, 0);
    stage_load(1, 1);
    stage_load(2, 2);

    for (int c = 0; c < 16; c++) {
        cp_wait2();
        __syncthreads();

        const uint32_t sb = smem_base + (uint32_t)(c % 3) * STAGE_B;
#pragma unroll
        for (int ks = 0; ks < 2; ks++) {
            const uint32_t a_co = (uint32_t)(((a_bc + ks * 2) ^ a_sw) << 4);
            const uint32_t b_co = (uint32_t)(((b_bc + ks * 2) ^ b_sw) << 4);
            uint32_t ah[2][4], al[2][4];
#pragma unroll
            for (int mt = 0; mt < 2; mt++) {
                ldsm_x4(ah[mt], sb + a_rb + mt * 1024 + a_co);
                ldsm_x4(al[mt], sb + 8192 + a_rb + mt * 1024 + a_co);
            }
#pragma unroll
            for (int p = 0; p < 4; p++) {
                uint32_t bh[4], bl[4];
                ldsm_x4(bh, sb + 16384 + b_rb + p * 1024 + b_co);
                ldsm_x4(bl, sb + 24576 + b_rb + p * 1024 + b_co);
#pragma unroll
                for (int mt = 0; mt < 2; mt++)
#pragma unroll
                    for (int h = 0; h < 2; h++)
                        mma16816(acc[mt][p * 2 + h], ah[mt], &bh[h * 2]);
#pragma unroll
                for (int mt = 0; mt < 2; mt++)
#pragma unroll
                    for (int h = 0; h < 2; h++)
                        mma16816(acc[mt][p * 2 + h], ah[mt], &bl[h * 2]);
#pragma unroll
                for (int mt = 0; mt < 2; mt++)
#pragma unroll
                    for (int h = 0; h < 2; h++)
                        mma16816(acc[mt][p * 2 + h], al[mt], &bh[h * 2]);
            }
        }

        __syncthreads();
        if (c + 3 < 16) stage_load(c + 3, c % 3);
        else cp_commit();                           // keep group count in lockstep
    }

    // epilogue: bias + fp32 store
    const int er = m0 + wm * 32 + (l >> 2);
    const int ec = n0 + wn * 64 + (l & 3) * 2;
#pragma unroll
    for (int mt = 0; mt < 2; mt++) {
        int r0 = er + mt * 16, r1 = r0 + 8;
#pragma unroll
        for (int nt = 0; nt < 8; nt++) {
            int cc = ec + nt * 8;
            float2 bi = *(const float2*)&g_bcat[cc];
            if (r0 < M) {
                float2 o = make_float2(acc[mt][nt][0] + bi.x, acc[mt][nt][1] + bi.y);
                *(float2*)&g_C[(size_t)r0 * 1024 + cc] = o;
            }
            if (r1 < M) {
                float2 o = make_float2(acc[mt][nt][2] + bi.x, acc[mt][nt][3] + bi.y);
                *(float2*)&g_C[(size_t)r1 * 1024 + cc] = o;
            }
        }
    }
}

// ---------------- attention kernel: one block per node + near-tie flagging ----------------
// v no longer staged in smem (context reads gmem via L1) -> 27 KB smem -> ~7 blocks/SM.
#define STR 516
__global__ __launch_bounds__(288) void attn_kernel(
    const float* __restrict__ emb, const float* __restrict__ ac,
    const float* __restrict__ Wg, const float* __restrict__ bg,
    const int* __restrict__ batch,
    float* __restrict__ ctx_out, float* __restrict__ att_out) {
    __shared__ float q[6][STR], k[6][STR];
    __shared__ float sc[8][6][6];
    __shared__ float at[8][6][6];
    __shared__ float g[6];

    const int n = blockIdx.x;
    const int tid = threadIdx.x;
    const float* Crow = g_C + (size_t)n * 6 * 1024;
    const float* Vrow = emb + (size_t)n * 6 * 512;

    for (int i = tid; i < 768; i += 288) {
        int t = i >> 7;
        int c4 = i & 127;
        float4 kv = *(const float4*)(Crow + t * 1024 + c4 * 4);
        float4 qv = *(const float4*)(Crow + t * 1024 + 512 + c4 * 4);
        *(float4*)&k[t][c4 * 4] = kv;
        *(float4*)&q[t][c4 * 4] = qv;
    }
    if (tid < 6) {
        int b = batch[n];
        float s = bg[tid];
#pragma unroll
        for (int j = 0; j < 5; j++) s += ac[b * 5 + j] * Wg[tid * 5 + j];
        g[tid] = s;
    }
    __syncthreads();

    {
        int h = tid / 36;
        int r = tid % 36;
        int t = r / 6;
        int s = r % 6;
        const float4* qp = (const float4*)&q[t][h * 64];
        const float4* kp = (const float4*)&k[s][h * 64];
        float acc = 0.f;
#pragma unroll
        for (int d = 0; d < 16; d++) {
            float4 a = qp[d];
            float4 b = kp[d];
            acc += a.x * b.x + a.y * b.y + a.z * b.z + a.w * b.w;
        }
        sc[h][t][s] = acc * 0.125f * g[s];
    }
    __syncthreads();

    if (tid < 48) {
        int h = tid / 6;
        int t = tid % 6;
        float a[6];
#pragma unroll
        for (int s = 0; s < 6; s++) a[s] = sc[h][t][s];
        bool keep[6];
        float a4 = 0.f, a5 = 0.f;
#pragma unroll
        for (int s = 0; s < 6; s++) {
            float as = fabsf(a[s]);
            int cnt = 0;
#pragma unroll
            for (int j = 0; j < 6; j++) {
                float aj = fabsf(a[j]);
                cnt += (aj > as) || (aj == as && j < s);
            }
            keep[s] = (cnt < 4);
            if (cnt == 3) a4 = as;
            if (cnt == 4) a5 = as;
        }
        // near-tie at the top-4 boundary: flag node for exact fp32 fixup
        if (a4 - a5 <= a4 * 1e-4f + 1e-7f) g_flag[n] = 1;

        float mx = -3.402823466e38f;
#pragma unroll
        for (int s = 0; s < 6; s++)
            if (keep[s]) mx = fmaxf(mx, a[s]);
        float e[6];
        float sum = 0.f;
#pragma unroll
        for (int s = 0; s < 6; s++) {
            e[s] = keep[s] ? expf(a[s] - mx) : 0.f;
            sum += e[s];
        }
        float inv = 1.f / sum;
#pragma unroll
        for (int s = 0; s < 6; s++) {
            float w = e[s] * inv;
            at[h][t][s] = w;
            if (att_out) att_out[(size_t)n * 288 + h * 36 + t * 6 + s] = w;
        }
    }
    __syncthreads();

    if (ctx_out) {
        for (int e = tid; e < 768; e += 288) {
            int t = e >> 7;
            int c4 = e & 127;
            int h = c4 >> 4;                        // (c4*4)>>6
            float4 o = make_float4(0.f, 0.f, 0.f, 0.f);
#pragma unroll
            for (int s = 0; s < 6; s++) {
                float4 v = *(const float4*)(Vrow + s * 512 + c4 * 4);
                float w = at[h][t][s];
                o.x += w * v.x; o.y += w * v.y; o.z += w * v.z; o.w += w * v.w;
            }
            *(float4*)&ctx_out[(size_t)n * 3072 + t * 512 + c4 * 4] = o;
        }
    }
}

// ---------------- fixup: exact fp32 recompute for flagged nodes ----------------
__global__ __launch_bounds__(288) void fixup_kernel(
    const float* __restrict__ emb, const float* __restrict__ ac,
    const float* __restrict__ Wk, const float* __restrict__ bk,
    const float* __restrict__ Wq, const float* __restrict__ bq,
    const float* __restrict__ Wg, const float* __restrict__ bg,
    const int* __restrict__ batch,
    float* __restrict__ ctx_out, float* __restrict__ att_out) {
    const int n = blockIdx.x;
    if (g_flag[n] == 0) return;

    __shared__ float x[6][512];
    __shared__ float kq[6][1024];
    __shared__ float sc[8][6][6];
    __shared__ float at[8][6][6];
    __shared__ float g[6];

    const int tid = threadIdx.x;
    const float* Xrow = emb + (size_t)n * 6 * 512;

    for (int i = tid; i < 768; i += 288) {
        int t = i >> 7, c4 = i & 127;
        *(float4*)&x[t][c4 * 4] = *(const float4*)(Xrow + t * 512 + c4 * 4);
    }
    if (tid < 6) {
        int b = batch[n];
        float s = bg[tid];
#pragma unroll
        for (int j = 0; j < 5; j++) s += ac[b * 5 + j] * Wg[tid * 5 + j];
        g[tid] = s;
    }
    __syncthreads();

    for (int idx = tid; idx < 6144; idx += 288) {
        int t = idx >> 10, j = idx & 1023;
        const float* w = (j < 512) ? (Wk + (size_t)j * 512) : (Wq + (size_t)(j - 512) * 512);
        float acc = (j < 512) ? bk[j] : bq[j - 512];
        const float4* wv = (const float4*)w;
        const float4* xv = (const float4*)&x[t][0];
#pragma unroll 4
        for (int d = 0; d < 128; d++) {
            float4 a = wv[d];
            float4 b = xv[d];
            acc += a.x * b.x + a.y * b.y + a.z * b.z + a.w * b.w;
        }
        kq[t][j] = acc;
    }
    __syncthreads();

    {
        int h = tid / 36;
        int r = tid % 36;
        int t = r / 6;
        int s = r % 6;
        const float* qp = &kq[t][512 + h * 64];
        const float* kp = &kq[s][h * 64];
        float acc = 0.f;
#pragma unroll
        for (int d = 0; d < 64; d++) acc += qp[d] * kp[d];
        sc[h][t][s] = acc * 0.125f * g[s];
    }
    __syncthreads();

    if (tid < 48) {
        int h = tid / 6;
        int t = tid % 6;
        float a[6];
#pragma unroll
        for (int s = 0; s < 6; s++) a[s] = sc[h][t][s];
        bool keep[6];
#pragma unroll
        for (int s = 0; s < 6; s++) {
            float as = fabsf(a[s]);
            int cnt = 0;
#pragma unroll
            for (int j = 0; j < 6; j++) {
                float aj = fabsf(a[j]);
                cnt += (aj > as) || (aj == as && j < s);
            }
            keep[s] = (cnt < 4);
        }
        float mx = -3.402823466e38f;
#pragma unroll
        for (int s = 0; s < 6; s++)
            if (keep[s]) mx = fmaxf(mx, a[s]);
        float e[6];
        float sum = 0.f;
#pragma unroll
        for (int s = 0; s < 6; s++) {
            e[s] = keep[s] ? expf(a[s] - mx) : 0.f;
            sum += e[s];
        }
        float inv = 1.f / sum;
#pragma unroll
        for (int s = 0; s < 6; s++) {
            float w = e[s] * inv;
            at[h][t][s] = w;
            if (att_out) att_out[(size_t)n * 288 + h * 36 + t * 6 + s] = w;
        }
    }
    __syncthreads();

    if (ctx_out) {
        for (int e = tid; e < 3072; e += 288) {
            int t = e >> 9;
            int c = e & 511;
            int h = c >> 6;
            float acc = 0.f;
#pragma unroll
            for (int s = 0; s < 6; s++) acc += at[h][t][s] * x[s][c];
            ctx_out[(size_t)n * 3072 + e] = acc;
        }
    }
}

// ---------------- launch ----------------
extern "C" void kernel_launch(void* const* d_in, const int* in_sizes, int n_in,
                              void* d_out, int out_size) {
    const float* emb = (const float*)d_in[0];
    const float* ac = (const float*)d_in[1];
    const float* Wk = (const float*)d_in[2];
    const float* bk = (const float*)d_in[3];
    const float* Wq = (const float*)d_in[4];
    const float* bq = (const float*)d_in[5];
    const float* Wg = (const float*)d_in[6];
    const float* bg = (const float*)d_in[7];
    const int* batch = (const int*)d_in[8];

    int nNodes = in_sizes[8];  // 30000
    int M = nNodes * 6;        // 180000

    float* out = (float*)d_out;
    long long CTX = (long long)nNodes * 6 * 512;
    long long ATT = (long long)nNodes * 8 * 36;
    float* ctx_out = nullptr;
    float* att_out = nullptr;
    if ((long long)out_size >= CTX + ATT) {
        ctx_out = out;
        att_out = out + CTX;
    } else if ((long long)out_size >= CTX) {
        ctx_out = out;
    } else {
        att_out = out;
    }

    cudaFuncSetAttribute(gemm_kernel, cudaFuncAttributeMaxDynamicSharedMemorySize,
                         SMEM_GEMM);

    pack_w<<<2048, 256>>>(Wk, bk, Wq, bq);
    int p4 = (M_PAD * 512) / 4;
    split_a<<<(p4 + 255) / 256, 256>>>(emb);
    dim3 gg(8, (M + 127) / 128);
    gemm_kernel<<<gg, 256, SMEM_GEMM>>>(M);
    attn_kernel<<<nNodes, 288>>>(emb, ac, Wg, bg, batch, ctx_out, att_out);
    fixup_kernel<<<nNodes, 288>>>(emb, ac, Wk, bk, Wq, bq, Wg, bg, batch,
                                  ctx_out, att_out);
}